// round 6
// baseline (speedup 1.0000x reference)
#include <cuda_runtime.h>
#include <cuda_bf16.h>

// One-hop neighbor sampling with replacement (EdgeSampler).
// KEY INSIGHT (round 6): the __output__ dtype is float32. Previous rounds
// wrote int32 bit patterns, which read back as float denormals ~1e-39 -> the
// checker saw an all-zero buffer -> rel_err exactly 1.0 every round.
// All output values (node ids < 1e6, bools) are < 2^24 so float32 is exact.
//
// Geometry: NUM_NODES=1e6, B=256, R=512, S=16 -> 131072 seeds, SEC=2097152.
// Output: float32 concat [src(SEC) | tgt(SEC) | valid(SEC)].
// Inputs bound on host by size ratios (valid under elements OR bytes units):
//   seeds = global-min, rand = 16x seeds, col = global-max, row = remaining.

#define SAMPLES  16
#define SPLIT    4                    // threads per seed
#define N_SEEDS  131072
#define N_THREADS (N_SEEDS * SPLIT)   // 524288
#define SECLL    ((long long)N_SEEDS * SAMPLES)   // 2097152

__global__ __launch_bounds__(256) void edge_sampler_kernel(
    const int*   __restrict__ seeds,
    const int*   __restrict__ rowp,
    const int*   __restrict__ col,
    const float4* __restrict__ rnd,      // [N_THREADS] float4
    char*  __restrict__ out_bytes,
    long long cap_bytes,
    int row_max_idx,                     // max legal index into rowp[i+1]
    long long col_max_idx)               // max legal index into col
{
    const int u = blockIdx.x * blockDim.x + threadIdx.x;
    if (u >= N_THREADS) return;

    const int t = u >> 2;                // seed index

    const int sid = seeds[t];
    int sid_c = sid;
    if (sid_c < 0) sid_c = 0;
    if (sid_c > row_max_idx) sid_c = row_max_idx;

    const int start = __ldg(&rowp[sid_c]);
    const int deg   = __ldg(&rowp[sid_c + 1]) - start;

    const float degf = (float)deg;
    const int   clampv = (deg > 0) ? (deg - 1) : 0;
    const float validf = (deg > 0) ? 1.0f : 0.0f;

    // 4 uniforms for this quad: one coalesced float4 per thread.
    const float4 uu = __ldg(&rnd[u]);
    const float us[4] = {uu.x, uu.y, uu.z, uu.w};

    // Gather positions (reference: idx = int(u*deg) clamped; pos=0 if deg==0).
    int pos[4];
    #pragma unroll
    for (int j = 0; j < 4; j++) {
        int idx = (int)(us[j] * degf);
        idx = min(idx, clampv);
        idx = max(idx, 0);
        long long p = (deg > 0) ? (long long)start + idx : 0;
        if (p < 0) p = 0;
        if (p > col_max_idx) p = col_max_idx;
        pos[j] = (int)p;
    }

    // 4 independent gathers (plus warp-level coalescing across the quad).
    int tg[4];
    #pragma unroll
    for (int j = 0; j < 4; j++) tg[j] = __ldg(&col[pos[j]]);

    // FLOAT32 output, flat [src | tgt | valid], float4 per thread per section.
    const float sidf = (float)sid;
    const float4 sv = make_float4(sidf, sidf, sidf, sidf);
    const float4 tv = make_float4((float)tg[0], (float)tg[1],
                                  (float)tg[2], (float)tg[3]);
    const float4 vv = make_float4(validf, validf, validf, validf);

    const long long elem = (long long)u * 4;           // float index in section
    long long off0 = elem * 4;                         // src byte offset
    long long off1 = (SECLL + elem) * 4;               // tgt
    long long off2 = (2 * SECLL + elem) * 4;           // valid

    if (off0 + 16 <= cap_bytes) *(float4*)(out_bytes + off0) = sv;
    if (off1 + 16 <= cap_bytes) *(float4*)(out_bytes + off1) = tv;
    if (off2 + 16 <= cap_bytes) *(float4*)(out_bytes + off2) = vv;
}

extern "C" void kernel_launch(void* const* d_in, const int* in_sizes, int n_in,
                              void* d_out, int out_size)
{
    // ---- Bind inputs by size ratios (order- and unit-invariant) ----
    int idx_seed = 0;
    for (int i = 1; i < n_in; i++)
        if (in_sizes[i] < in_sizes[idx_seed]) idx_seed = i;

    int idx_col = 0;
    for (int i = 1; i < n_in; i++)
        if (in_sizes[i] > in_sizes[idx_col]) idx_col = i;

    int idx_rand = -1;
    for (int i = 0; i < n_in; i++) {
        if (i != idx_seed && i != idx_col &&
            (long long)in_sizes[i] == 16LL * (long long)in_sizes[idx_seed]) {
            idx_rand = i; break;
        }
    }
    int idx_row = -1;
    for (int i = 0; i < n_in; i++)
        if (i != idx_seed && i != idx_col && i != idx_rand) { idx_row = i; break; }
    if (idx_rand < 0) idx_rand = idx_row;   // degenerate fallback

    const int*    seeds = (const int*)d_in[idx_seed];
    const int*    rowp  = (const int*)d_in[idx_row];
    const int*    col   = (const int*)d_in[idx_col];
    const float4* rnd   = (const float4*)d_in[idx_rand];

    // Read clamps from reported sizes. If sizes are in BYTES these clamps are
    // looser than reality, but actual data values (sid < 1e6, pos < num_edges)
    // keep accesses in true bounds; clamps only protect against corrupt data.
    int row_max_idx = in_sizes[idx_row] - 2;         // rowp[i+1] must be legal
    if (row_max_idx < 0) row_max_idx = 0;
    long long col_max_idx = (long long)in_sizes[idx_col] - 1;
    if (col_max_idx < 0) col_max_idx = 0;

    // Output capacity in bytes; never write beyond logical output either way.
    long long cap_bytes = (long long)out_size * 4;   // out_size = float32 elems
    const long long full = 3 * SECLL * 4;            // 25165824
    if (cap_bytes > full) cap_bytes = full;

    const int threads = 256;
    const int blocks  = (N_THREADS + threads - 1) / threads;   // 2048
    edge_sampler_kernel<<<blocks, threads>>>(
        seeds, rowp, col, rnd,
        (char*)d_out, cap_bytes, row_max_idx, col_max_idx);
}

// round 7
// speedup vs baseline: 1.0208x; 1.0208x over previous
#include <cuda_runtime.h>
#include <cuda_bf16.h>

// One-hop neighbor sampling with replacement (EdgeSampler), float32 output.
// Geometry: NUM_NODES=1e6, B=256, R=512, S=16 -> 131072 seeds, SEC=2097152.
// Output: float32 concat [src(SEC) | tgt(SEC) | valid(SEC)].
//
// R7: latency-bound per ncu (issue 24.7%, DRAM 44.5%). Each thread now owns
// TWO independent seed-quads (quad u and quad u + T), doubling MLP at every
// stage of the dependent chain (seed -> row_ptr -> gather). 262144 threads
// ~= one full-occupancy wave.

#define SAMPLES   16
#define N_SEEDS   131072
#define N_QUADS   (N_SEEDS * 4)        // 524288
#define N_THREADS (N_QUADS / 2)        // 262144
#define SECLL     ((long long)N_SEEDS * SAMPLES)   // 2097152

__global__ __launch_bounds__(256) void edge_sampler_kernel(
    const int*    __restrict__ seeds,
    const int*    __restrict__ rowp,
    const int*    __restrict__ col,
    const float4* __restrict__ rnd,      // [N_QUADS] float4
    char*  __restrict__ out_bytes,
    long long cap_bytes,
    int row_max_idx,
    long long col_max_idx)
{
    const int u = blockIdx.x * blockDim.x + threadIdx.x;
    if (u >= N_THREADS) return;

    const int q0 = u;
    const int q1 = u + N_THREADS;
    const int t0 = q0 >> 2;
    const int t1 = q1 >> 2;

    // ---- Stage 1: two independent seed loads (batched) ----
    const int sid0 = __ldg(&seeds[t0]);
    const int sid1 = __ldg(&seeds[t1]);

    int c0 = min(max(sid0, 0), row_max_idx);
    int c1 = min(max(sid1, 0), row_max_idx);

    // ---- Stage 2: four independent row_ptr loads (batched) ----
    const int s0 = __ldg(&rowp[c0]);
    const int e0 = __ldg(&rowp[c0 + 1]);
    const int s1 = __ldg(&rowp[c1]);
    const int e1 = __ldg(&rowp[c1 + 1]);

    // rand loads are independent of the above; issue early too.
    const float4 r0 = __ldg(&rnd[q0]);
    const float4 r1 = __ldg(&rnd[q1]);

    const int d0 = e0 - s0;
    const int d1 = e1 - s1;
    const float df0 = (float)d0;
    const float df1 = (float)d1;
    const int cl0 = (d0 > 0) ? (d0 - 1) : 0;
    const int cl1 = (d1 > 0) ? (d1 - 1) : 0;
    const float v0 = (d0 > 0) ? 1.0f : 0.0f;
    const float v1 = (d1 > 0) ? 1.0f : 0.0f;

    // ---- Stage 3: compute 8 gather positions, issue 8 gathers together ----
    const float us0[4] = {r0.x, r0.y, r0.z, r0.w};
    const float us1[4] = {r1.x, r1.y, r1.z, r1.w};

    int pos0[4], pos1[4];
    #pragma unroll
    for (int j = 0; j < 4; j++) {
        int i0 = (int)(us0[j] * df0);
        i0 = max(min(i0, cl0), 0);
        long long p0 = (d0 > 0) ? (long long)s0 + i0 : 0;
        p0 = (p0 < 0) ? 0 : (p0 > col_max_idx ? col_max_idx : p0);
        pos0[j] = (int)p0;

        int i1 = (int)(us1[j] * df1);
        i1 = max(min(i1, cl1), 0);
        long long p1 = (d1 > 0) ? (long long)s1 + i1 : 0;
        p1 = (p1 < 0) ? 0 : (p1 > col_max_idx ? col_max_idx : p1);
        pos1[j] = (int)p1;
    }

    int tg0[4], tg1[4];
    #pragma unroll
    for (int j = 0; j < 4; j++) tg0[j] = __ldg(&col[pos0[j]]);
    #pragma unroll
    for (int j = 0; j < 4; j++) tg1[j] = __ldg(&col[pos1[j]]);

    // ---- Stores: float4, coalesced; 6 stores (2 quads x 3 sections) ----
    const float sf0 = (float)sid0;
    const float sf1 = (float)sid1;

    const long long e0ll = (long long)q0 * 4;   // float index within a section
    const long long e1ll = (long long)q1 * 4;

    const long long off_s0 = e0ll * 4;
    const long long off_s1 = e1ll * 4;
    const long long off_t0 = (SECLL + e0ll) * 4;
    const long long off_t1 = (SECLL + e1ll) * 4;
    const long long off_v0 = (2 * SECLL + e0ll) * 4;
    const long long off_v1 = (2 * SECLL + e1ll) * 4;

    if (off_s0 + 16 <= cap_bytes)
        *(float4*)(out_bytes + off_s0) = make_float4(sf0, sf0, sf0, sf0);
    if (off_s1 + 16 <= cap_bytes)
        *(float4*)(out_bytes + off_s1) = make_float4(sf1, sf1, sf1, sf1);
    if (off_t0 + 16 <= cap_bytes)
        *(float4*)(out_bytes + off_t0) = make_float4((float)tg0[0], (float)tg0[1],
                                                     (float)tg0[2], (float)tg0[3]);
    if (off_t1 + 16 <= cap_bytes)
        *(float4*)(out_bytes + off_t1) = make_float4((float)tg1[0], (float)tg1[1],
                                                     (float)tg1[2], (float)tg1[3]);
    if (off_v0 + 16 <= cap_bytes)
        *(float4*)(out_bytes + off_v0) = make_float4(v0, v0, v0, v0);
    if (off_v1 + 16 <= cap_bytes)
        *(float4*)(out_bytes + off_v1) = make_float4(v1, v1, v1, v1);
}

extern "C" void kernel_launch(void* const* d_in, const int* in_sizes, int n_in,
                              void* d_out, int out_size)
{
    // ---- Bind inputs by size ratios (order- and unit-invariant) ----
    int idx_seed = 0;
    for (int i = 1; i < n_in; i++)
        if (in_sizes[i] < in_sizes[idx_seed]) idx_seed = i;

    int idx_col = 0;
    for (int i = 1; i < n_in; i++)
        if (in_sizes[i] > in_sizes[idx_col]) idx_col = i;

    int idx_rand = -1;
    for (int i = 0; i < n_in; i++) {
        if (i != idx_seed && i != idx_col &&
            (long long)in_sizes[i] == 16LL * (long long)in_sizes[idx_seed]) {
            idx_rand = i; break;
        }
    }
    int idx_row = -1;
    for (int i = 0; i < n_in; i++)
        if (i != idx_seed && i != idx_col && i != idx_rand) { idx_row = i; break; }
    if (idx_rand < 0) idx_rand = idx_row;

    const int*    seeds = (const int*)d_in[idx_seed];
    const int*    rowp  = (const int*)d_in[idx_row];
    const int*    col   = (const int*)d_in[idx_col];
    const float4* rnd   = (const float4*)d_in[idx_rand];

    int row_max_idx = in_sizes[idx_row] - 2;
    if (row_max_idx < 0) row_max_idx = 0;
    long long col_max_idx = (long long)in_sizes[idx_col] - 1;
    if (col_max_idx < 0) col_max_idx = 0;

    long long cap_bytes = (long long)out_size * 4;
    const long long full = 3 * SECLL * 4;
    if (cap_bytes > full) cap_bytes = full;

    const int threads = 256;
    const int blocks  = (N_THREADS + threads - 1) / threads;   // 1024
    edge_sampler_kernel<<<blocks, threads>>>(
        seeds, rowp, col, rnd,
        (char*)d_out, cap_bytes, row_max_idx, col_max_idx);
}